// round 16
// baseline (speedup 1.0000x reference)
#include <cuda_runtime.h>

#define Bz 8
#define Tz 32
#define Sz 256
#define Dz 1024
#define Mz (Bz*Tz)      // 256
#define K2z (2*Dz)      // 2048
#define WPARTS 64       // column-sum stage-1 partials
#define NOUT (Bz*Tz*Sz) // 65536

// Scratch (device globals — no allocations allowed)
__device__ float g_s[Mz*K2z];        // [256][2048]  s1|s2, masked prefix means
__device__ float g_q[4][Mz*Dz];      // q partials per split-K quarter
__device__ float g_w[Dz];            // colsum of W_v
__device__ float g_wpart[WPARTS*Dz]; // stage-1 partial colsums
__device__ float g_pab[Bz*Sz*4];     // {pa0,pa1,pb0,pb1} per (b,s)
__device__ float g_sum[NOUT];        // accumulated sum_gate (zeroed by prep each call)

// ---------------- helpers ----------------
__device__ __forceinline__ unsigned long long pk2(float lo, float hi) {
    unsigned long long r;
    asm("mov.b64 %0, {%1, %2};" : "=l"(r) : "r"(__float_as_uint(lo)), "r"(__float_as_uint(hi)));
    return r;
}
__device__ __forceinline__ void fma2(unsigned long long& d, unsigned long long a, unsigned long long b) {
    asm("fma.rn.f32x2 %0, %1, %2, %0;" : "+l"(d) : "l"(a), "l"(b));
}
__device__ __forceinline__ void unpk2(unsigned long long v, float& lo, float& hi) {
    unsigned int a, b;
    asm("mov.b64 {%0, %1}, %2;" : "=r"(a), "=r"(b) : "l"(v));
    lo = __uint_as_float(a); hi = __uint_as_float(b);
}
__device__ __forceinline__ float tanh_fast(float x) {
    float y;
    asm("tanh.approx.f32 %0, %1;" : "=f"(y) : "f"(x));
    return y;
}

// ---------------- prep: zero g_sum + s build + colsum stage1 (112 blocks) ----------------
__global__ void __launch_bounds__(256) prep_kernel(
    const float* __restrict__ src1, const float* __restrict__ src2,
    const float* __restrict__ mask1, const float* __restrict__ mask2,
    const float* __restrict__ Wv)
{
    int blk = blockIdx.x;
    int tid = threadIdx.x;
    if (blk < 16) {
        ((float4*)g_sum)[blk * 1024 + tid] = make_float4(0.f, 0.f, 0.f, 0.f);
        ((float4*)g_sum)[blk * 1024 + 256 + tid] = make_float4(0.f, 0.f, 0.f, 0.f);
        ((float4*)g_sum)[blk * 1024 + 512 + tid] = make_float4(0.f, 0.f, 0.f, 0.f);
        ((float4*)g_sum)[blk * 1024 + 768 + tid] = make_float4(0.f, 0.f, 0.f, 0.f);
    } else if (blk < 48) {
        // prefix-mean: one thread per (b,d)
        int g = (blk - 16) * 256 + tid;
        int b = g >> 10;
        int d = g & 1023;
        float r1 = 0.f, r2 = 0.f;
        #pragma unroll
        for (int t = 0; t < Tz; t++) {
            int row = b * Tz + t;
            r1 += src1[row * Dz + d];
            r2 += src2[row * Dz + d];
            float inv = 1.0f / (float)(t + 1);
            g_s[row * K2z + d]      = r1 * inv * mask1[row];
            g_s[row * K2z + Dz + d] = r2 * inv * mask2[row];
        }
    } else {
        // colsum stage 1: block bb sums Wv rows [bb*16, bb*16+16)
        int bb = blk - 48;                   // 0..63
        const float4* Wv4 = (const float4*)Wv;
        int j0 = bb * 16;
        float4 acc = make_float4(0.f, 0.f, 0.f, 0.f);
        #pragma unroll
        for (int j = 0; j < 16; j++) {
            float4 v = Wv4[(j0 + j) * 256 + tid];
            acc.x += v.x; acc.y += v.y; acc.z += v.z; acc.w += v.w;
        }
        ((float4*)g_wpart)[bb * 256 + tid] = acc;
    }
}

// ---------------- GEMM (+ folded wsum stage2): pk2-A / packed-B FFMA2 inner loop ----------------
#define BM 64
#define BN 64
#define KC 16
#define KHALF 512
#define LDA 68

__global__ void __launch_bounds__(256) gemm_kernel(
    const float* __restrict__ W1, const float* __restrict__ W2,
    const float* __restrict__ bq1, const float* __restrict__ bq2)
{
    __shared__ __align__(16) float sa[KC * LDA];   // [k][m]
    __shared__ __align__(16) float sb[KC * LDA];   // [k][n]

    int blk = blockIdx.x;
    int tid = threadIdx.x;

    if (blk >= 256) {
        // folded wsum: colsum stage 2 (4 blocks x 256 threads = 1024 d)
        int d = (blk - 256) * 256 + tid;
        float acc = 0.f;
        #pragma unroll
        for (int p = 0; p < WPARTS; p++) acc += g_wpart[p * Dz + d];
        g_w[d] = acc;
        return;
    }

    int bm = blk & 3;
    int bn = (blk >> 2) & 15;
    int kz = blk >> 6;          // 0..3 = kw*2 + kh
    int kw = kz >> 1, kh = kz & 1;
    const float* Wmat = (kw ? W2 : W1) + kh * KHALF;
    const float* A = g_s + kw * Dz + kh * KHALF;
    float* Cout = g_q[kz];

    int tx = tid & 15, ty = tid >> 4;
    int lm = tid >> 2, kq = tid & 3;
    int mBase = bm * BM, nBase = bn * BN;

    unsigned long long acc[4][2];
    #pragma unroll
    for (int i = 0; i < 4; i++) { acc[i][0] = 0ull; acc[i][1] = 0ull; }

    // prefetch first slab
    float4 av = *(const float4*)&A[(mBase + lm) * K2z + kq * 4];
    float4 bv = *(const float4*)&Wmat[(nBase + lm) * Dz + kq * 4];

    for (int k0 = 0; k0 < KHALF; k0 += KC) {
        __syncthreads();
        sa[(kq * 4 + 0) * LDA + lm] = av.x;
        sa[(kq * 4 + 1) * LDA + lm] = av.y;
        sa[(kq * 4 + 2) * LDA + lm] = av.z;
        sa[(kq * 4 + 3) * LDA + lm] = av.w;
        sb[(kq * 4 + 0) * LDA + lm] = bv.x;
        sb[(kq * 4 + 1) * LDA + lm] = bv.y;
        sb[(kq * 4 + 2) * LDA + lm] = bv.z;
        sb[(kq * 4 + 3) * LDA + lm] = bv.w;
        __syncthreads();
        if (k0 + KC < KHALF) {
            av = *(const float4*)&A[(mBase + lm) * K2z + k0 + KC + kq * 4];
            bv = *(const float4*)&Wmat[(nBase + lm) * Dz + k0 + KC + kq * 4];
        }
        #pragma unroll
        for (int kk = 0; kk < KC; kk++) {
            float4 a4 = *(const float4*)&sa[kk * LDA + ty * 4];
            // B pairs loaded directly as packed f32x2 operands (contiguous n floats)
            ulonglong2 b03 = *(const ulonglong2*)&sb[kk * LDA + tx * 4];
            unsigned long long aup;
            aup = pk2(a4.x, a4.x); fma2(acc[0][0], aup, b03.x); fma2(acc[0][1], aup, b03.y);
            aup = pk2(a4.y, a4.y); fma2(acc[1][0], aup, b03.x); fma2(acc[1][1], aup, b03.y);
            aup = pk2(a4.z, a4.z); fma2(acc[2][0], aup, b03.x); fma2(acc[2][1], aup, b03.y);
            aup = pk2(a4.w, a4.w); fma2(acc[3][0], aup, b03.x); fma2(acc[3][1], aup, b03.y);
        }
    }

    int n0 = nBase + tx * 4;
    float bb0 = 0.f, bb1 = 0.f, bb2 = 0.f, bb3 = 0.f;
    if (kz == 0) {
        bb0 = bq1[n0 + 0] + bq2[n0 + 0];
        bb1 = bq1[n0 + 1] + bq2[n0 + 1];
        bb2 = bq1[n0 + 2] + bq2[n0 + 2];
        bb3 = bq1[n0 + 3] + bq2[n0 + 3];
    }
    #pragma unroll
    for (int i = 0; i < 4; i++) {
        int m = mBase + ty * 4 + i;
        float v0, v1, v2, v3;
        unpk2(acc[i][0], v0, v1);
        unpk2(acc[i][1], v2, v3);
        float4 o = make_float4(v0 + bb0, v1 + bb1, v2 + bb2, v3 + bb3);
        *(float4*)&Cout[m * Dz + n0] = o;
    }
}

// ---------------- main: tanh-gate reduction (+ folded pa/pb) ----------------
// blocks [0,512): b(8) x tt(4) x ds(16); block 256 = 8 warps; lane owns one s,
//   8 t-accumulators in registers. smem mem tile [256 s][32 d] stride 33.
// blocks [512,768): pa/pb, one warp per (b,s) — only consumed by combine_kernel.
#define SUBD 33

__global__ void __launch_bounds__(256) main_kernel(
    const float* __restrict__ mem, const float* __restrict__ Wc)
{
    __shared__ float ms[Sz * SUBD];   // 33.8 KB
    __shared__ float qs[8 * 32];
    __shared__ float ws[32];

    int blk = blockIdx.x;
    int tid = threadIdx.x;

    if (blk >= 512) {
        // folded pa/pb: one warp per (b,s), vectorized float4
        int widx = (blk - 512) * 8 + (tid >> 5);  // 0..2047
        int lane = tid & 31;
        int b = widx >> 8, s2 = widx & 255;
        const float4* mrow = (const float4*)(mem + (b * Sz + s2) * Dz);
        const float4* w0p = (const float4*)(Wc);
        const float4* w1p = (const float4*)(Wc + K2z);
        const float4* w2p = (const float4*)(Wc + Dz);
        const float4* w3p = (const float4*)(Wc + K2z + Dz);
        float a0 = 0.f, a1 = 0.f, p0 = 0.f, p1 = 0.f;
        #pragma unroll
        for (int it = 0; it < 8; it++) {
            int d4 = it * 32 + lane;          // float4 index
            float4 mv = mrow[d4];
            float4 w0 = w0p[d4], w1 = w1p[d4], w2 = w2p[d4], w3 = w3p[d4];
            a0 = fmaf(mv.x, w0.x, fmaf(mv.y, w0.y, fmaf(mv.z, w0.z, fmaf(mv.w, w0.w, a0))));
            a1 = fmaf(mv.x, w1.x, fmaf(mv.y, w1.y, fmaf(mv.z, w1.z, fmaf(mv.w, w1.w, a1))));
            p0 = fmaf(mv.x, w2.x, fmaf(mv.y, w2.y, fmaf(mv.z, w2.z, fmaf(mv.w, w2.w, p0))));
            p1 = fmaf(mv.x, w3.x, fmaf(mv.y, w3.y, fmaf(mv.z, w3.z, fmaf(mv.w, w3.w, p1))));
        }
        #pragma unroll
        for (int o = 16; o; o >>= 1) {
            a0 += __shfl_down_sync(~0u, a0, o);
            a1 += __shfl_down_sync(~0u, a1, o);
            p0 += __shfl_down_sync(~0u, p0, o);
            p1 += __shfl_down_sync(~0u, p1, o);
        }
        if (!lane) {
            float4 v = make_float4(a0, a1, p0, p1);
            *(float4*)&g_pab[(b * Sz + s2) * 4] = v;
        }
        return;
    }

    int ds = blk & 15;
    int tt = (blk >> 4) & 3;
    int b  = blk >> 6;
    int t0 = tt * 8;
    int d0 = ds * 64;

    int warp = tid >> 5, lane = tid & 31;
    int s = warp * 32 + lane;

    float acc[8];
    #pragma unroll
    for (int t = 0; t < 8; t++) acc[t] = 0.f;

    #pragma unroll
    for (int sc = 0; sc < 2; sc++) {
        int db = d0 + sc * 32;
        // load mem tile [256 s][32 d] -> ms[s*33 + d]
        #pragma unroll
        for (int k = 0; k < 8; k++) {
            int j = tid + k * 256;
            int srow = j >> 3, dq = j & 7;
            float4 v = *(const float4*)&mem[(b * Sz + srow) * Dz + db + dq * 4];
            int base = srow * SUBD + dq * 4;
            ms[base + 0] = v.x; ms[base + 1] = v.y;
            ms[base + 2] = v.z; ms[base + 3] = v.w;
        }
        // load q tile (sum of 4 partials): 8 t x 32 d
        if (tid < 64) {
            int t = tid >> 3, dq = tid & 7;
            int row = b * Tz + t0 + t;
            int off = row * Dz + db + dq * 4;
            float4 q0 = *(const float4*)&g_q[0][off];
            float4 q1 = *(const float4*)&g_q[1][off];
            float4 q2 = *(const float4*)&g_q[2][off];
            float4 q3 = *(const float4*)&g_q[3][off];
            int base = t * 32 + dq * 4;
            qs[base + 0] = (q0.x + q1.x) + (q2.x + q3.x);
            qs[base + 1] = (q0.y + q1.y) + (q2.y + q3.y);
            qs[base + 2] = (q0.z + q1.z) + (q2.z + q3.z);
            qs[base + 3] = (q0.w + q1.w) + (q2.w + q3.w);
        }
        if (tid < 8) {
            float4 wv = *(const float4*)&g_w[db + tid * 4];
            ws[tid * 4 + 0] = wv.x; ws[tid * 4 + 1] = wv.y;
            ws[tid * 4 + 2] = wv.z; ws[tid * 4 + 3] = wv.w;
        }
        __syncthreads();

        #pragma unroll 4
        for (int d = 0; d < 32; d++) {
            float m  = ms[s * SUBD + d];
            float wv = ws[d];
            #pragma unroll
            for (int t = 0; t < 8; t++)
                acc[t] = fmaf(wv, tanh_fast(qs[t * 32 + d] + m), acc[t]);
        }
        __syncthreads();
    }

    #pragma unroll
    for (int t = 0; t < 8; t++)
        atomicAdd(&g_sum[(b * Tz + t0 + t) * Sz + s], acc[t]);
}

// ---------------- epilogue ----------------
__global__ void __launch_bounds__(256) combine_kernel(
    const float* __restrict__ bcate, float* __restrict__ out)
{
    int g = blockIdx.x * 256 + threadIdx.x;   // 0..65535 = (b*32+t)*256+s
    float p = g_sum[g];
    int s = g & 255;
    int b = g >> 13;
    float4 pab = *(const float4*)&g_pab[(b * Sz + s) * 4];
    float2 o;
    o.x = fmaf(p, pab.z, pab.x) + bcate[0];
    o.y = fmaf(p, pab.w, pab.y) + bcate[1];
    *(float2*)&out[g * 2] = o;
}

extern "C" void kernel_launch(void* const* d_in, const int* in_sizes, int n_in,
                              void* d_out, int out_size) {
    const float* src1  = (const float*)d_in[0];
    const float* src2  = (const float*)d_in[1];
    const float* mem   = (const float*)d_in[2];
    const float* mask1 = (const float*)d_in[3];
    const float* mask2 = (const float*)d_in[4];
    const float* Wq1   = (const float*)d_in[5];
    const float* bq1   = (const float*)d_in[6];
    const float* Wq2   = (const float*)d_in[7];
    const float* bq2   = (const float*)d_in[8];
    const float* Wc    = (const float*)d_in[9];
    const float* bc    = (const float*)d_in[10];
    const float* Wv    = (const float*)d_in[11];
    float* out = (float*)d_out;

    prep_kernel<<<112, 256>>>(src1, src2, mask1, mask2, Wv);
    gemm_kernel<<<260, 256>>>(Wq1, Wq2, bq1, bq2);
    main_kernel<<<768, 256>>>(mem, Wc);
    combine_kernel<<<256, 256>>>(bc, out);
}

// round 17
// speedup vs baseline: 1.0225x; 1.0225x over previous
#include <cuda_runtime.h>

#define Bz 8
#define Tz 32
#define Sz 256
#define Dz 1024
#define Mz (Bz*Tz)      // 256
#define K2z (2*Dz)      // 2048
#define WPARTS 64       // column-sum stage-1 partials
#define NQ 8            // split-K partial buffers
#define NOUT (Bz*Tz*Sz) // 65536

// Scratch (device globals — no allocations allowed)
__device__ float g_s[Mz*K2z];        // [256][2048]  s1|s2, masked prefix means
__device__ float g_q[NQ][Mz*Dz];     // q partials per split-K eighth
__device__ float g_w[Dz];            // colsum of W_v
__device__ float g_wpart[WPARTS*Dz]; // stage-1 partial colsums
__device__ float g_pab[Bz*Sz*4];     // {pa0,pa1,pb0,pb1} per (b,s)
__device__ float g_sum[NOUT];        // accumulated sum_gate (zeroed by prep each call)

// ---------------- helpers ----------------
__device__ __forceinline__ unsigned long long pk2(float lo, float hi) {
    unsigned long long r;
    asm("mov.b64 %0, {%1, %2};" : "=l"(r) : "r"(__float_as_uint(lo)), "r"(__float_as_uint(hi)));
    return r;
}
__device__ __forceinline__ void fma2(unsigned long long& d, unsigned long long a, unsigned long long b) {
    asm("fma.rn.f32x2 %0, %1, %2, %0;" : "+l"(d) : "l"(a), "l"(b));
}
__device__ __forceinline__ void unpk2(unsigned long long v, float& lo, float& hi) {
    unsigned int a, b;
    asm("mov.b64 {%0, %1}, %2;" : "=r"(a), "=r"(b) : "l"(v));
    lo = __uint_as_float(a); hi = __uint_as_float(b);
}
__device__ __forceinline__ float tanh_fast(float x) {
    float y;
    asm("tanh.approx.f32 %0, %1;" : "=f"(y) : "f"(x));
    return y;
}

// ---------------- prep: zero g_sum + s build + colsum stage1 (112 blocks) ----------------
__global__ void __launch_bounds__(256) prep_kernel(
    const float* __restrict__ src1, const float* __restrict__ src2,
    const float* __restrict__ mask1, const float* __restrict__ mask2,
    const float* __restrict__ Wv)
{
    int blk = blockIdx.x;
    int tid = threadIdx.x;
    if (blk < 16) {
        ((float4*)g_sum)[blk * 1024 + tid] = make_float4(0.f, 0.f, 0.f, 0.f);
        ((float4*)g_sum)[blk * 1024 + 256 + tid] = make_float4(0.f, 0.f, 0.f, 0.f);
        ((float4*)g_sum)[blk * 1024 + 512 + tid] = make_float4(0.f, 0.f, 0.f, 0.f);
        ((float4*)g_sum)[blk * 1024 + 768 + tid] = make_float4(0.f, 0.f, 0.f, 0.f);
    } else if (blk < 48) {
        // prefix-mean: one thread per (b,d)
        int g = (blk - 16) * 256 + tid;
        int b = g >> 10;
        int d = g & 1023;
        float r1 = 0.f, r2 = 0.f;
        #pragma unroll
        for (int t = 0; t < Tz; t++) {
            int row = b * Tz + t;
            r1 += src1[row * Dz + d];
            r2 += src2[row * Dz + d];
            float inv = 1.0f / (float)(t + 1);
            g_s[row * K2z + d]      = r1 * inv * mask1[row];
            g_s[row * K2z + Dz + d] = r2 * inv * mask2[row];
        }
    } else {
        // colsum stage 1: block bb sums Wv rows [bb*16, bb*16+16)
        int bb = blk - 48;                   // 0..63
        const float4* Wv4 = (const float4*)Wv;
        int j0 = bb * 16;
        float4 acc = make_float4(0.f, 0.f, 0.f, 0.f);
        #pragma unroll
        for (int j = 0; j < 16; j++) {
            float4 v = Wv4[(j0 + j) * 256 + tid];
            acc.x += v.x; acc.y += v.y; acc.z += v.z; acc.w += v.w;
        }
        ((float4*)g_wpart)[bb * 256 + tid] = acc;
    }
}

// ---------------- GEMM (+ folded wsum stage2): pk2 FFMA2, split-K=8 ----------------
#define BM 64
#define BN 64
#define KC 16
#define KQRT 256
#define LDA 68

__global__ void __launch_bounds__(256) gemm_kernel(
    const float* __restrict__ W1, const float* __restrict__ W2,
    const float* __restrict__ bq1, const float* __restrict__ bq2)
{
    __shared__ float sa[KC * LDA];   // [k][m]
    __shared__ float sb[KC * LDA];   // [k][n]

    int blk = blockIdx.x;
    int tid = threadIdx.x;

    if (blk >= 512) {
        // folded wsum: colsum stage 2 (4 blocks x 256 threads = 1024 d)
        int d = (blk - 512) * 256 + tid;
        float acc = 0.f;
        #pragma unroll
        for (int p = 0; p < WPARTS; p++) acc += g_wpart[p * Dz + d];
        g_w[d] = acc;
        return;
    }

    int bm = blk & 3;
    int bn = (blk >> 2) & 15;
    int kz = blk >> 6;          // 0..7 = kw*4 + kh
    int kw = kz >> 2, kh = kz & 3;
    const float* Wmat = (kw ? W2 : W1) + kh * KQRT;
    const float* A = g_s + kw * Dz + kh * KQRT;
    float* Cout = g_q[kz];

    int tx = tid & 15, ty = tid >> 4;
    int lm = tid >> 2, kq = tid & 3;
    int mBase = bm * BM, nBase = bn * BN;

    unsigned long long acc[4][2];
    #pragma unroll
    for (int i = 0; i < 4; i++) { acc[i][0] = 0ull; acc[i][1] = 0ull; }

    // prefetch first slab
    float4 av = *(const float4*)&A[(mBase + lm) * K2z + kq * 4];
    float4 bv = *(const float4*)&Wmat[(nBase + lm) * Dz + kq * 4];

    for (int k0 = 0; k0 < KQRT; k0 += KC) {
        __syncthreads();
        sa[(kq * 4 + 0) * LDA + lm] = av.x;
        sa[(kq * 4 + 1) * LDA + lm] = av.y;
        sa[(kq * 4 + 2) * LDA + lm] = av.z;
        sa[(kq * 4 + 3) * LDA + lm] = av.w;
        sb[(kq * 4 + 0) * LDA + lm] = bv.x;
        sb[(kq * 4 + 1) * LDA + lm] = bv.y;
        sb[(kq * 4 + 2) * LDA + lm] = bv.z;
        sb[(kq * 4 + 3) * LDA + lm] = bv.w;
        __syncthreads();
        if (k0 + KC < KQRT) {
            av = *(const float4*)&A[(mBase + lm) * K2z + k0 + KC + kq * 4];
            bv = *(const float4*)&Wmat[(nBase + lm) * Dz + k0 + KC + kq * 4];
        }
        #pragma unroll
        for (int kk = 0; kk < KC; kk++) {
            float4 a4 = *(const float4*)&sa[kk * LDA + ty * 4];
            float4 b4 = *(const float4*)&sb[kk * LDA + tx * 4];
            unsigned long long b01 = pk2(b4.x, b4.y);
            unsigned long long b23 = pk2(b4.z, b4.w);
            unsigned long long aup;
            aup = pk2(a4.x, a4.x); fma2(acc[0][0], aup, b01); fma2(acc[0][1], aup, b23);
            aup = pk2(a4.y, a4.y); fma2(acc[1][0], aup, b01); fma2(acc[1][1], aup, b23);
            aup = pk2(a4.z, a4.z); fma2(acc[2][0], aup, b01); fma2(acc[2][1], aup, b23);
            aup = pk2(a4.w, a4.w); fma2(acc[3][0], aup, b01); fma2(acc[3][1], aup, b23);
        }
    }

    int n0 = nBase + tx * 4;
    float bb0 = 0.f, bb1 = 0.f, bb2 = 0.f, bb3 = 0.f;
    if (kz == 0) {
        bb0 = bq1[n0 + 0] + bq2[n0 + 0];
        bb1 = bq1[n0 + 1] + bq2[n0 + 1];
        bb2 = bq1[n0 + 2] + bq2[n0 + 2];
        bb3 = bq1[n0 + 3] + bq2[n0 + 3];
    }
    #pragma unroll
    for (int i = 0; i < 4; i++) {
        int m = mBase + ty * 4 + i;
        float v0, v1, v2, v3;
        unpk2(acc[i][0], v0, v1);
        unpk2(acc[i][1], v2, v3);
        float4 o = make_float4(v0 + bb0, v1 + bb1, v2 + bb2, v3 + bb3);
        *(float4*)&Cout[m * Dz + n0] = o;
    }
}

// ---------------- main: tanh-gate reduction (+ folded pa/pb) ----------------
// blocks [0,512): b(8) x tt(4) x ds(16); block 256 = 8 warps; lane owns one s,
//   8 t-accumulators in registers. smem mem tile [256 s][32 d] stride 33.
// blocks [512,768): pa/pb, one warp per (b,s) — only consumed by combine_kernel.
#define SUBD 33

__global__ void __launch_bounds__(256) main_kernel(
    const float* __restrict__ mem, const float* __restrict__ Wc)
{
    __shared__ float ms[Sz * SUBD];   // 33.8 KB
    __shared__ float qs[8 * 32];
    __shared__ float ws[32];

    int blk = blockIdx.x;
    int tid = threadIdx.x;

    if (blk >= 512) {
        // folded pa/pb: one warp per (b,s), vectorized float4
        int widx = (blk - 512) * 8 + (tid >> 5);  // 0..2047
        int lane = tid & 31;
        int b = widx >> 8, s2 = widx & 255;
        const float4* mrow = (const float4*)(mem + (b * Sz + s2) * Dz);
        const float4* w0p = (const float4*)(Wc);
        const float4* w1p = (const float4*)(Wc + K2z);
        const float4* w2p = (const float4*)(Wc + Dz);
        const float4* w3p = (const float4*)(Wc + K2z + Dz);
        float a0 = 0.f, a1 = 0.f, p0 = 0.f, p1 = 0.f;
        #pragma unroll
        for (int it = 0; it < 8; it++) {
            int d4 = it * 32 + lane;          // float4 index
            float4 mv = mrow[d4];
            float4 w0 = w0p[d4], w1 = w1p[d4], w2 = w2p[d4], w3 = w3p[d4];
            a0 = fmaf(mv.x, w0.x, fmaf(mv.y, w0.y, fmaf(mv.z, w0.z, fmaf(mv.w, w0.w, a0))));
            a1 = fmaf(mv.x, w1.x, fmaf(mv.y, w1.y, fmaf(mv.z, w1.z, fmaf(mv.w, w1.w, a1))));
            p0 = fmaf(mv.x, w2.x, fmaf(mv.y, w2.y, fmaf(mv.z, w2.z, fmaf(mv.w, w2.w, p0))));
            p1 = fmaf(mv.x, w3.x, fmaf(mv.y, w3.y, fmaf(mv.z, w3.z, fmaf(mv.w, w3.w, p1))));
        }
        #pragma unroll
        for (int o = 16; o; o >>= 1) {
            a0 += __shfl_down_sync(~0u, a0, o);
            a1 += __shfl_down_sync(~0u, a1, o);
            p0 += __shfl_down_sync(~0u, p0, o);
            p1 += __shfl_down_sync(~0u, p1, o);
        }
        if (!lane) {
            float4 v = make_float4(a0, a1, p0, p1);
            *(float4*)&g_pab[(b * Sz + s2) * 4] = v;
        }
        return;
    }

    int ds = blk & 15;
    int tt = (blk >> 4) & 3;
    int b  = blk >> 6;
    int t0 = tt * 8;
    int d0 = ds * 64;

    int warp = tid >> 5, lane = tid & 31;
    int s = warp * 32 + lane;

    float acc[8];
    #pragma unroll
    for (int t = 0; t < 8; t++) acc[t] = 0.f;

    #pragma unroll
    for (int sc = 0; sc < 2; sc++) {
        int db = d0 + sc * 32;
        // load mem tile [256 s][32 d] -> ms[s*33 + d]
        #pragma unroll
        for (int k = 0; k < 8; k++) {
            int j = tid + k * 256;
            int srow = j >> 3, dq = j & 7;
            float4 v = *(const float4*)&mem[(b * Sz + srow) * Dz + db + dq * 4];
            int base = srow * SUBD + dq * 4;
            ms[base + 0] = v.x; ms[base + 1] = v.y;
            ms[base + 2] = v.z; ms[base + 3] = v.w;
        }
        // load q tile (sum of 8 partials): 8 t x 32 d
        if (tid < 64) {
            int t = tid >> 3, dq = tid & 7;
            int row = b * Tz + t0 + t;
            int off = row * Dz + db + dq * 4;
            float4 q0 = *(const float4*)&g_q[0][off];
            float4 q1 = *(const float4*)&g_q[1][off];
            float4 q2 = *(const float4*)&g_q[2][off];
            float4 q3 = *(const float4*)&g_q[3][off];
            float4 q4 = *(const float4*)&g_q[4][off];
            float4 q5 = *(const float4*)&g_q[5][off];
            float4 q6 = *(const float4*)&g_q[6][off];
            float4 q7 = *(const float4*)&g_q[7][off];
            int base = t * 32 + dq * 4;
            qs[base + 0] = ((q0.x + q1.x) + (q2.x + q3.x)) + ((q4.x + q5.x) + (q6.x + q7.x));
            qs[base + 1] = ((q0.y + q1.y) + (q2.y + q3.y)) + ((q4.y + q5.y) + (q6.y + q7.y));
            qs[base + 2] = ((q0.z + q1.z) + (q2.z + q3.z)) + ((q4.z + q5.z) + (q6.z + q7.z));
            qs[base + 3] = ((q0.w + q1.w) + (q2.w + q3.w)) + ((q4.w + q5.w) + (q6.w + q7.w));
        }
        if (tid < 8) {
            float4 wv = *(const float4*)&g_w[db + tid * 4];
            ws[tid * 4 + 0] = wv.x; ws[tid * 4 + 1] = wv.y;
            ws[tid * 4 + 2] = wv.z; ws[tid * 4 + 3] = wv.w;
        }
        __syncthreads();

        #pragma unroll 4
        for (int d = 0; d < 32; d++) {
            float m  = ms[s * SUBD + d];
            float wv = ws[d];
            #pragma unroll
            for (int t = 0; t < 8; t++)
                acc[t] = fmaf(wv, tanh_fast(qs[t * 32 + d] + m), acc[t]);
        }
        __syncthreads();
    }

    #pragma unroll
    for (int t = 0; t < 8; t++)
        atomicAdd(&g_sum[(b * Tz + t0 + t) * Sz + s], acc[t]);
}

// ---------------- epilogue ----------------
__global__ void __launch_bounds__(256) combine_kernel(
    const float* __restrict__ bcate, float* __restrict__ out)
{
    int g = blockIdx.x * 256 + threadIdx.x;   // 0..65535 = (b*32+t)*256+s
    float p = g_sum[g];
    int s = g & 255;
    int b = g >> 13;
    float4 pab = *(const float4*)&g_pab[(b * Sz + s) * 4];
    float2 o;
    o.x = fmaf(p, pab.z, pab.x) + bcate[0];
    o.y = fmaf(p, pab.w, pab.y) + bcate[1];
    *(float2*)&out[g * 2] = o;
}

extern "C" void kernel_launch(void* const* d_in, const int* in_sizes, int n_in,
                              void* d_out, int out_size) {
    const float* src1  = (const float*)d_in[0];
    const float* src2  = (const float*)d_in[1];
    const float* mem   = (const float*)d_in[2];
    const float* mask1 = (const float*)d_in[3];
    const float* mask2 = (const float*)d_in[4];
    const float* Wq1   = (const float*)d_in[5];
    const float* bq1   = (const float*)d_in[6];
    const float* Wq2   = (const float*)d_in[7];
    const float* bq2   = (const float*)d_in[8];
    const float* Wc    = (const float*)d_in[9];
    const float* bc    = (const float*)d_in[10];
    const float* Wv    = (const float*)d_in[11];
    float* out = (float*)d_out;

    prep_kernel<<<112, 256>>>(src1, src2, mask1, mask2, Wv);
    gemm_kernel<<<516, 256>>>(Wq1, Wq2, bq1, bq2);
    main_kernel<<<768, 256>>>(mem, Wc);
    combine_kernel<<<256, 256>>>(bc, out);
}